// round 10
// baseline (speedup 1.0000x reference)
#include <cuda_runtime.h>
#include <cuda_fp16.h>
#include <cstdint>

// ---------------------------------------------------------------------------
// SparseMPNNLayer — all four MLPs via mma.sync m16n8k16 fp16 (fp32 accum).
// Edge kernel: tile=64 edges, 2 CTAs/SM, vector RED scatter.
//   pass1: msg = MLP([h_v[src], h_u[dst], e_feat]) -> red.v4 scatter m_u[dst]
//          deg[src] += 1
//   node1: h_u_out = MLP([h_u, m_u/S])
//   pass2: msg = MLP([h_u_out[dst], h_v[src], e_feat]) -> scatter m_v[src]
//   node2: h_v_out = MLP([h_v, m_v/max(deg,1)])
// ---------------------------------------------------------------------------

#define NTPB 256
#define ETPB 256
constexpr int HD = 64;
constexpr int MAXN = 100000;

__device__ float g_m_u[(size_t)MAXN * HD];
__device__ float g_m_v[(size_t)MAXN * HD];
__device__ float g_deg[MAXN];

// ---- edge smem layout (32-bit words; each word = 2 halves) ----------------
constexpr int EW1_OFF = 0;                     // [128 n][192 k]h  (12288 w)
constexpr int EW2_OFF = EW1_OFF + 128 * 96;    // [64 n][128 k]h   (4096 w)
constexpr int EX_OFF  = EW2_OFF + 64 * 64;     // [64 e][192 k]h   (6144 w)
                                               //   scatter buf aliases X:
                                               //   [64 e][68 f32] (4352 w)
constexpr int EH_OFF  = EX_OFF + 64 * 96;      // [64 e][128 h]h   (4096 w)
constexpr int EB1_OFF = EH_OFF + 64 * 64;      // 128 f32
constexpr int EB2_OFF = EB1_OFF + 128;         // 64 f32
constexpr int EDGE_SMEM = (EB2_OFF + 64) * 4;  // 107264 B  (x2 CTA = 214.5KB)

// ---- node smem layout (words) ---------------------------------------------
constexpr int NW1_OFF = 0;                     // [64 n][128 k]h
constexpr int NW2_OFF = NW1_OFF + 64 * 64;     // [64 n][64 k]h
constexpr int NX_OFF  = NW2_OFF + 64 * 32;     // [128 r][128 k]h
constexpr int NH_OFF  = NX_OFF + 128 * 64;     // [128 r][64 h]h
constexpr int NB1_OFF = NH_OFF + 128 * 32;     // 64 f32
constexpr int NB2_OFF = NB1_OFF + 64;          // 64 f32
constexpr int NODE_SMEM = (NB2_OFF + 64) * 4;  // 74240 B

__device__ __forceinline__ uint32_t p2h(float a, float b) {
    __half2 h = __floats2half2_rn(a, b);   // low = a
    return *(uint32_t*)&h;
}
__device__ __forceinline__ uint4 pack8(float4 a, float4 b) {
    uint4 r;
    r.x = p2h(a.x, a.y); r.y = p2h(a.z, a.w);
    r.z = p2h(b.x, b.y); r.w = p2h(b.z, b.w);
    return r;
}

__device__ __forceinline__ void mma16(float* c, uint32_t a0, uint32_t a1,
                                      uint32_t a2, uint32_t a3,
                                      uint32_t b0, uint32_t b1) {
    asm("mma.sync.aligned.m16n8k16.row.col.f32.f16.f16.f32 "
        "{%0,%1,%2,%3}, {%4,%5,%6,%7}, {%8,%9}, {%0,%1,%2,%3};"
        : "+f"(c[0]), "+f"(c[1]), "+f"(c[2]), "+f"(c[3])
        : "r"(a0), "r"(a1), "r"(a2), "r"(a3), "r"(b0), "r"(b1));
}

// XOR-swizzled 16B-chunk store: row stride in words, chunk = 16B unit index.
__device__ __forceinline__ void st_chunk(uint32_t* b, int row, int stride,
                                         int chunk, uint4 v) {
    const int c = (chunk & ~7) | ((chunk & 7) ^ (row & 7));
    *(uint4*)(b + row * stride + c * 4) = v;
}

__device__ __forceinline__ void red4(float* p, float4 v) {
    asm volatile("red.global.add.v4.f32 [%0], {%1,%2,%3,%4};"
                 :: "l"(p), "f"(v.x), "f"(v.y), "f"(v.z), "f"(v.w) : "memory");
}

// ---------------------------------------------------------------------------
// Edge MLP: x = [A[idxA[e]] | B[idxB[e]] | EF[e]] (192) -> relu(x@W1+b1) (128)
//           -> @W2+b2 (64) -> red.v4 scatter accum[idxOut[e]]
// Tile = 64 edges, 8 warps, 2 CTAs/SM.
// GEMM1 warp: 16e x 64h. GEMM2 warp: 16e x 32o.
// ---------------------------------------------------------------------------
__global__ void __launch_bounds__(ETPB, 2) edge_mlp_tc(
    const float* __restrict__ A, const int* __restrict__ idxA,
    const float* __restrict__ B, const int* __restrict__ idxB,
    const float* __restrict__ EF, const int* __restrict__ idxOut,
    const float* __restrict__ W1, const float* __restrict__ b1,
    const float* __restrict__ W2, const float* __restrict__ b2,
    float* __restrict__ accum, float* __restrict__ deg, int E)
{
    extern __shared__ uint32_t smu[];
    uint32_t* W1s = smu + EW1_OFF;
    uint32_t* W2s = smu + EW2_OFF;
    uint32_t* Xs  = smu + EX_OFF;
    float*    Sc  = (float*)(smu + EX_OFF);   // scatter buf, aliases X
    uint32_t* Hs  = smu + EH_OFF;
    float* sB1 = (float*)(smu + EB1_OFF);
    float* sB2 = (float*)(smu + EB2_OFF);

    const int tid = threadIdx.x;
    const int warp = tid >> 5, lane = tid & 31;
    const int g = lane >> 2, t = lane & 3;

    // ---- one-time: weights -> [n][k] halves, swizzled ---------------------
    for (int i = tid; i < 96 * 128; i += ETPB) {
        const int kp = i >> 7, n = i & 127;
        const int ch = kp >> 2;
        const int cc = (ch & ~7) | ((ch & 7) ^ (n & 7));
        W1s[n * 96 + cc * 4 + (kp & 3)] =
            p2h(W1[(2 * kp) * 128 + n], W1[(2 * kp + 1) * 128 + n]);
    }
    for (int i = tid; i < 64 * 64; i += ETPB) {
        const int kp = i >> 6, n = i & 63;
        const int ch = kp >> 2;
        const int cc = (ch & ~7) | ((ch & 7) ^ (n & 7));
        W2s[n * 64 + cc * 4 + (kp & 3)] =
            p2h(W2[(2 * kp) * 64 + n], W2[(2 * kp + 1) * 64 + n]);
    }
    if (tid < 128) sB1[tid] = b1[tid];
    if (tid < 64)  sB2[tid] = b2[tid];
    __syncthreads();

    int off3[8];
    #pragma unroll
    for (int c = 0; c < 8; c++) off3[c] = ((c ^ g) << 2) + t;

    const int m0 = (warp >> 1) * 16;       // 16 edge rows per warp
    const int n0 = (warp & 1) * 64;        // GEMM1 cols
    const int nb = (warp & 1) * 32;        // GEMM2 cols

    const int arA0 = (m0 + g) * 96,  arA1 = (m0 + g + 8) * 96;
    const int arH0 = (m0 + g) * 64,  arH1 = (m0 + g + 8) * 64;
    int brB[8], br2[4];
    #pragma unroll
    for (int ni = 0; ni < 8; ni++) brB[ni] = (n0 + ni * 8 + g) * 96;
    #pragma unroll
    for (int ni = 0; ni < 4; ni++) br2[ni] = (nb + ni * 8 + g) * 64;

    const int el = tid >> 2, q = tid & 3;  // staging/RED: 64 edges x 4 threads
    const int ntiles = (E + 63) >> 6;

    for (int tile = blockIdx.x; tile < ntiles; tile += gridDim.x) {
        const int base = tile << 6;

        // ---- stage X [64 rows][24 chunks]: gather, fp16, swizzled ---------
        {
            const int ge = base + el;
            if (ge < E) {
                const float4* srcA = (const float4*)(A + (size_t)idxA[ge] * HD);
                const float4* srcB = (const float4*)(B + (size_t)idxB[ge] * HD);
                const float4* srcE = (const float4*)(EF + (size_t)ge * HD);
                #pragma unroll
                for (int i = 0; i < 6; i++) {
                    const int c = q * 6 + i;                 // chunk 0..23
                    const int sid = c >> 3, off = c & 7;     // 0=A,1=B,2=EF
                    const float4* s = (sid == 0) ? srcA : (sid == 1) ? srcB : srcE;
                    st_chunk(Xs, el, 96, c, pack8(s[2 * off], s[2 * off + 1]));
                }
            }
        }
        __syncthreads();   // (1) X ready

        // ---- GEMM1: 16e x 64h, K=192 (12 k16 steps) ----
        float c1[8][4];
        #pragma unroll
        for (int ni = 0; ni < 8; ni++)
            #pragma unroll
            for (int p = 0; p < 4; p++) c1[ni][p] = 0.0f;

        #pragma unroll
        for (int ks = 0; ks < 12; ks++) {
            const int C0 = 2 * ks, C1 = 2 * ks + 1;
            const int o0 = ((C0 & ~7) << 2) + off3[C0 & 7];
            const int o1 = ((C1 & ~7) << 2) + off3[C1 & 7];
            const uint32_t a0 = Xs[arA0 + o0], a1 = Xs[arA1 + o0];
            const uint32_t a2 = Xs[arA0 + o1], a3 = Xs[arA1 + o1];
            #pragma unroll
            for (int ni = 0; ni < 8; ni++)
                mma16(c1[ni], a0, a1, a2, a3,
                      W1s[brB[ni] + o0], W1s[brB[ni] + o1]);
        }

        // ---- epilogue 1: relu(c1 + b1) -> H (fp16, swizzled) ----
        {
            const int r0 = m0 + g;
            #pragma unroll
            for (int ni = 0; ni < 8; ni++) {
                const int col = n0 + ni * 8 + 2 * t;
                const float2 bb = *(const float2*)(sB1 + col);
                const int ch = (n0 >> 3) + ni;
                const int cc = (ch & ~7) | ((ch & 7) ^ g);
                const int wo = cc * 4 + t;
                Hs[r0 * 64 + wo] =
                    p2h(fmaxf(c1[ni][0] + bb.x, 0.0f),
                        fmaxf(c1[ni][1] + bb.y, 0.0f));
                Hs[(r0 + 8) * 64 + wo] =
                    p2h(fmaxf(c1[ni][2] + bb.x, 0.0f),
                        fmaxf(c1[ni][3] + bb.y, 0.0f));
            }
        }
        if (deg != nullptr && tid < 64) {
            const int ge = base + tid;
            if (ge < E) atomicAdd(deg + idxA[ge], 1.0f);
        }
        __syncthreads();   // (2) H ready (X reads also all done)

        // ---- GEMM2: 16e x 32o, K=128 (8 k16 steps) ----
        float c2[4][4];
        #pragma unroll
        for (int ni = 0; ni < 4; ni++)
            #pragma unroll
            for (int p = 0; p < 4; p++) c2[ni][p] = 0.0f;

        #pragma unroll
        for (int ks = 0; ks < 8; ks++) {
            const int C0 = 2 * ks, C1 = 2 * ks + 1;
            const int o0 = ((C0 & ~7) << 2) + off3[C0 & 7];
            const int o1 = ((C1 & ~7) << 2) + off3[C1 & 7];
            const uint32_t a0 = Hs[arH0 + o0], a1 = Hs[arH1 + o0];
            const uint32_t a2 = Hs[arH0 + o1], a3 = Hs[arH1 + o1];
            #pragma unroll
            for (int ni = 0; ni < 4; ni++)
                mma16(c2[ni], a0, a1, a2, a3,
                      W2s[br2[ni] + o0], W2s[br2[ni] + o1]);
        }

        // ---- write c2 + b2 into scatter buffer (fp32, stride 68) ----
        {
            const int r0 = m0 + g;
            #pragma unroll
            for (int ni = 0; ni < 4; ni++) {
                const int col = nb + ni * 8 + 2 * t;
                const float2 bb = *(const float2*)(sB2 + col);
                *(float2*)(Sc + r0 * 68 + col) =
                    make_float2(c2[ni][0] + bb.x, c2[ni][1] + bb.y);
                *(float2*)(Sc + (r0 + 8) * 68 + col) =
                    make_float2(c2[ni][2] + bb.x, c2[ni][3] + bb.y);
            }
        }
        __syncthreads();   // (3) scatter buffer ready

        // ---- vector RED scatter: 4x red.v4 per thread ----
        {
            const int ge = base + el;
            if (ge < E) {
                const int d = idxOut[ge];
                float* dst = accum + (size_t)d * HD + q * 16;
                const float* srow = Sc + el * 68 + q * 16;
                #pragma unroll
                for (int j = 0; j < 4; j++) {
                    float4 v = *(const float4*)(srow + 4 * j);
                    red4(dst + 4 * j, v);
                }
            }
        }
        __syncthreads();   // (4) RED reads done; X/Sc free for next tile
    }
}

// ---------------------------------------------------------------------------
// Node MLP: x = [self[i] | msum[i]*scale] (128) -> relu(x@W1+b1) (64)
//           -> @W2+b2 (64) -> direct store. 2 CTAs/SM.
// ---------------------------------------------------------------------------
__global__ void __launch_bounds__(NTPB, 2) node_mlp_tc(
    const float* __restrict__ selfF, const float* __restrict__ msum,
    const float* __restrict__ deg, const int* __restrict__ Sp,
    const float* __restrict__ W1, const float* __restrict__ b1,
    const float* __restrict__ W2, const float* __restrict__ b2,
    float* __restrict__ out, int N)
{
    extern __shared__ uint32_t smu[];
    uint32_t* W1s = smu + NW1_OFF;
    uint32_t* W2s = smu + NW2_OFF;
    uint32_t* Xs  = smu + NX_OFF;
    uint32_t* Hs  = smu + NH_OFF;
    float* sB1 = (float*)(smu + NB1_OFF);
    float* sB2 = (float*)(smu + NB2_OFF);

    const int tid = threadIdx.x;
    const int warp = tid >> 5, lane = tid & 31;
    const int g = lane >> 2, t = lane & 3;

    for (int i = tid; i < 64 * 64; i += NTPB) {
        const int kp = i >> 6, n = i & 63;
        const int ch = kp >> 2;
        const int cc = (ch & ~7) | ((ch & 7) ^ (n & 7));
        W1s[n * 64 + cc * 4 + (kp & 3)] =
            p2h(W1[(2 * kp) * 64 + n], W1[(2 * kp + 1) * 64 + n]);
    }
    for (int i = tid; i < 32 * 64; i += NTPB) {
        const int kp = i >> 6, n = i & 63;
        const int ch = kp >> 2;
        const int cc = (ch & ~7) | ((ch & 7) ^ (n & 7));
        W2s[n * 32 + cc * 4 + (kp & 3)] =
            p2h(W2[(2 * kp) * 64 + n], W2[(2 * kp + 1) * 64 + n]);
    }
    if (tid < 64) { sB1[tid] = b1[tid]; sB2[tid] = b2[tid]; }
    __syncthreads();

    const float invS = (Sp != nullptr) ? (1.0f / (float)(*Sp)) : 0.0f;

    int off3[8];
    #pragma unroll
    for (int c = 0; c < 8; c++) off3[c] = ((c ^ g) << 2) + t;

    const int m0 = (warp >> 1) * 32;
    const int n0 = (warp & 1) * 32;

    int arX[2][2], arH[2][2], brB[4], br2[4];
    #pragma unroll
    for (int mi = 0; mi < 2; mi++) {
        arX[mi][0] = (m0 + mi * 16 + g) * 64;
        arX[mi][1] = (m0 + mi * 16 + g + 8) * 64;
        arH[mi][0] = (m0 + mi * 16 + g) * 32;
        arH[mi][1] = (m0 + mi * 16 + g + 8) * 32;
    }
    #pragma unroll
    for (int ni = 0; ni < 4; ni++) {
        brB[ni] = (n0 + ni * 8 + g) * 64;
        br2[ni] = (n0 + ni * 8 + g) * 32;
    }

    const int sr = tid >> 1, half = tid & 1;
    const int ntiles = (N + 127) >> 7;

    for (int tile = blockIdx.x; tile < ntiles; tile += gridDim.x) {
        const int base = tile << 7;

        // ---- stage X [128 rows][16 chunks] ----
        {
            const int i = base + sr;
            if (i < N) {
                if (half == 0) {
                    const float4* s = (const float4*)(selfF + (size_t)i * HD);
                    #pragma unroll
                    for (int j = 0; j < 8; j++)
                        st_chunk(Xs, sr, 64, j, pack8(s[2 * j], s[2 * j + 1]));
                } else {
                    const float sc = (Sp != nullptr) ? invS
                                                     : (1.0f / fmaxf(deg[i], 1.0f));
                    const float4* m = (const float4*)(msum + (size_t)i * HD);
                    #pragma unroll
                    for (int j = 0; j < 8; j++) {
                        float4 v0 = m[2 * j], v1 = m[2 * j + 1];
                        v0.x *= sc; v0.y *= sc; v0.z *= sc; v0.w *= sc;
                        v1.x *= sc; v1.y *= sc; v1.z *= sc; v1.w *= sc;
                        st_chunk(Xs, sr, 64, 8 + j, pack8(v0, v1));
                    }
                }
            }
        }
        __syncthreads();   // (1) X ready

        // ---- GEMM1: 32r x 32h, K=128 (8 steps) ----
        float c1[2][4][4];
        #pragma unroll
        for (int mi = 0; mi < 2; mi++)
            #pragma unroll
            for (int ni = 0; ni < 4; ni++)
                #pragma unroll
                for (int p = 0; p < 4; p++) c1[mi][ni][p] = 0.0f;

        #pragma unroll
        for (int ks = 0; ks < 8; ks++) {
            const int C0 = 2 * ks, C1 = 2 * ks + 1;
            const int o0 = ((C0 & ~7) << 2) + off3[C0 & 7];
            const int o1 = ((C1 & ~7) << 2) + off3[C1 & 7];
            uint32_t a[2][4];
            #pragma unroll
            for (int mi = 0; mi < 2; mi++) {
                a[mi][0] = Xs[arX[mi][0] + o0];
                a[mi][1] = Xs[arX[mi][1] + o0];
                a[mi][2] = Xs[arX[mi][0] + o1];
                a[mi][3] = Xs[arX[mi][1] + o1];
            }
            uint32_t b[4][2];
            #pragma unroll
            for (int ni = 0; ni < 4; ni++) {
                b[ni][0] = W1s[brB[ni] + o0];
                b[ni][1] = W1s[brB[ni] + o1];
            }
            #pragma unroll
            for (int mi = 0; mi < 2; mi++)
                #pragma unroll
                for (int ni = 0; ni < 4; ni++)
                    mma16(c1[mi][ni], a[mi][0], a[mi][1], a[mi][2], a[mi][3],
                          b[ni][0], b[ni][1]);
        }

        // ---- epilogue 1: relu -> H (fp16, stride 32 words) ----
        #pragma unroll
        for (int mi = 0; mi < 2; mi++) {
            const int r0 = m0 + mi * 16 + g;
            #pragma unroll
            for (int ni = 0; ni < 4; ni++) {
                const int col = n0 + ni * 8 + 2 * t;
                const float2 bb = *(const float2*)(sB1 + col);
                const int ch = (n0 >> 3) + ni;
                const int cc = (ch & ~7) | ((ch & 7) ^ g);
                const int wo = cc * 4 + t;
                Hs[r0 * 32 + wo] =
                    p2h(fmaxf(c1[mi][ni][0] + bb.x, 0.0f),
                        fmaxf(c1[mi][ni][1] + bb.y, 0.0f));
                Hs[(r0 + 8) * 32 + wo] =
                    p2h(fmaxf(c1[mi][ni][2] + bb.x, 0.0f),
                        fmaxf(c1[mi][ni][3] + bb.y, 0.0f));
            }
        }
        __syncthreads();   // (2) H ready

        // ---- GEMM2: 32r x 32o, K=64 (4 steps) ----
        float c2[2][4][4];
        #pragma unroll
        for (int mi = 0; mi < 2; mi++)
            #pragma unroll
            for (int ni = 0; ni < 4; ni++)
                #pragma unroll
                for (int p = 0; p < 4; p++) c2[mi][ni][p] = 0.0f;

        #pragma unroll
        for (int ks = 0; ks < 4; ks++) {
            const int C0 = 2 * ks, C1 = 2 * ks + 1;
            const int o0 = ((C0 & ~7) << 2) + off3[C0 & 7];
            const int o1 = ((C1 & ~7) << 2) + off3[C1 & 7];
            uint32_t a[2][4];
            #pragma unroll
            for (int mi = 0; mi < 2; mi++) {
                a[mi][0] = Hs[arH[mi][0] + o0];
                a[mi][1] = Hs[arH[mi][1] + o0];
                a[mi][2] = Hs[arH[mi][0] + o1];
                a[mi][3] = Hs[arH[mi][1] + o1];
            }
            uint32_t b[4][2];
            #pragma unroll
            for (int ni = 0; ni < 4; ni++) {
                b[ni][0] = W2s[br2[ni] + o0];
                b[ni][1] = W2s[br2[ni] + o1];
            }
            #pragma unroll
            for (int mi = 0; mi < 2; mi++)
                #pragma unroll
                for (int ni = 0; ni < 4; ni++)
                    mma16(c2[mi][ni], a[mi][0], a[mi][1], a[mi][2], a[mi][3],
                          b[ni][0], b[ni][1]);
        }

        // ---- epilogue 2: + b2, direct store ----
        #pragma unroll
        for (int mi = 0; mi < 2; mi++) {
            const int r0 = m0 + mi * 16 + g;
            const int gi0 = base + r0, gi1 = gi0 + 8;
            #pragma unroll
            for (int ni = 0; ni < 4; ni++) {
                const int col = n0 + ni * 8 + 2 * t;
                const float2 bb = *(const float2*)(sB2 + col);
                if (gi0 < N)
                    *(float2*)(out + (size_t)gi0 * HD + col) =
                        make_float2(c2[mi][ni][0] + bb.x, c2[mi][ni][1] + bb.y);
                if (gi1 < N)
                    *(float2*)(out + (size_t)gi1 * HD + col) =
                        make_float2(c2[mi][ni][2] + bb.x, c2[mi][ni][3] + bb.y);
            }
        }
        __syncthreads();   // H reads done before next tile staging
    }
}

// ---------------------------------------------------------------------------
extern "C" void kernel_launch(void* const* d_in, const int* in_sizes, int n_in,
                              void* d_out, int out_size)
{
    const float* h_v    = (const float*)d_in[0];
    const float* h_u    = (const float*)d_in[1];
    const float* e_feat = (const float*)d_in[2];
    const int*   ei     = (const int*)d_in[3];
    const int*   Sp     = (const int*)d_in[4];
    const float* a2u_w1 = (const float*)d_in[5];
    const float* a2u_b1 = (const float*)d_in[6];
    const float* a2u_w2 = (const float*)d_in[7];
    const float* a2u_b2 = (const float*)d_in[8];
    const float* u_w1   = (const float*)d_in[9];
    const float* u_b1   = (const float*)d_in[10];
    const float* u_w2   = (const float*)d_in[11];
    const float* u_b2   = (const float*)d_in[12];
    const float* u2a_w1 = (const float*)d_in[13];
    const float* u2a_b1 = (const float*)d_in[14];
    const float* u2a_w2 = (const float*)d_in[15];
    const float* u2a_b2 = (const float*)d_in[16];
    const float* a_w1   = (const float*)d_in[17];
    const float* a_b1   = (const float*)d_in[18];
    const float* a_w2   = (const float*)d_in[19];
    const float* a_b2   = (const float*)d_in[20];

    const int NVn = in_sizes[0] / HD;
    const int NUn = in_sizes[1] / HD;
    const int E   = in_sizes[3] / 2;
    const int* src = ei;
    const int* dst = ei + E;

    float *m_u = nullptr, *m_v = nullptr, *degp = nullptr;
    cudaGetSymbolAddress((void**)&m_u, g_m_u);
    cudaGetSymbolAddress((void**)&m_v, g_m_v);
    cudaGetSymbolAddress((void**)&degp, g_deg);

    int sms = 148;
    cudaDeviceGetAttribute(&sms, cudaDevAttrMultiProcessorCount, 0);

    cudaFuncSetAttribute(edge_mlp_tc,
                         cudaFuncAttributeMaxDynamicSharedMemorySize, EDGE_SMEM);
    cudaFuncSetAttribute(node_mlp_tc,
                         cudaFuncAttributeMaxDynamicSharedMemorySize, NODE_SMEM);

    cudaMemsetAsync(m_u,  0, (size_t)NUn * HD * sizeof(float));
    cudaMemsetAsync(m_v,  0, (size_t)NVn * HD * sizeof(float));
    cudaMemsetAsync(degp, 0, (size_t)NVn * sizeof(float));

    float* h_v_out = (float*)d_out;
    float* h_u_out = (float*)d_out + (size_t)NVn * HD;

    const int etiles = (E + 63) >> 6;
    const int egrid = etiles < 2 * sms ? etiles : 2 * sms;
    const int nutiles = (NUn + 127) >> 7;
    const int nvtiles = (NVn + 127) >> 7;
    const int ngrid_u = nutiles < 2 * sms ? nutiles : 2 * sms;
    const int ngrid_v = nvtiles < 2 * sms ? nvtiles : 2 * sms;

    // Pass 1: a -> u messages, scatter to m_u[dst]; count deg[src]
    edge_mlp_tc<<<egrid, ETPB, EDGE_SMEM>>>(
        h_v, src, h_u, dst, e_feat, dst,
        a2u_w1, a2u_b1, a2u_w2, a2u_b2, m_u, degp, E);

    // u node update
    node_mlp_tc<<<ngrid_u, NTPB, NODE_SMEM>>>(
        h_u, m_u, nullptr, Sp,
        u_w1, u_b1, u_w2, u_b2, h_u_out, NUn);

    // Pass 2: u -> a messages, scatter to m_v[src]
    edge_mlp_tc<<<egrid, ETPB, EDGE_SMEM>>>(
        h_u_out, dst, h_v, src, e_feat, src,
        u2a_w1, u2a_b1, u2a_w2, u2a_b2, m_v, nullptr, E);

    // v node update
    node_mlp_tc<<<ngrid_v, NTPB, NODE_SMEM>>>(
        h_v, m_v, degp, nullptr,
        a_w1, a_b1, a_w2, a_b2, h_v_out, NVn);
}

// round 11
// speedup vs baseline: 1.3332x; 1.3332x over previous
#include <cuda_runtime.h>
#include <cuda_fp16.h>
#include <cstdint>

// ---------------------------------------------------------------------------
// SparseMPNNLayer — all four MLPs via mma.sync m16n8k16 fp16 (fp32 accum).
// Edge kernel: 128-edge tile, 1 CTA/SM, double-buffered X with register
// prefetch of the next tile's gather (hidden under GEMM1).
//   pass1: msg = MLP([h_v[src], h_u[dst], e_feat]) -> atomic scatter m_u[dst]
//          deg[src] += 1
//   node1: h_u_out = MLP([h_u, m_u/S])
//   pass2: msg = MLP([h_u_out[dst], h_v[src], e_feat]) -> scatter m_v[src]
//   node2: h_v_out = MLP([h_v, m_v/max(deg,1)])
// ---------------------------------------------------------------------------

#define NTPB 256
#define ETPB 256
constexpr int HD = 64;
constexpr int MAXN = 100000;

__device__ float g_m_u[(size_t)MAXN * HD];
__device__ float g_m_v[(size_t)MAXN * HD];
__device__ float g_deg[MAXN];

// ---- edge smem layout (32-bit words; each word = 2 halves) ----------------
constexpr int EW1_OFF = 0;                     // [128 n][192 k]h  (12288 w)
constexpr int EW2_OFF = EW1_OFF + 128 * 96;    // [64 n][128 k]h   (4096 w)
constexpr int EX0_OFF = EW2_OFF + 64 * 64;     // X buf 0 [128 e][192 k]h
constexpr int EX1_OFF = EX0_OFF + 128 * 96;    // X buf 1
constexpr int EH_OFF  = EX1_OFF + 128 * 96;    // [128 e][128 h]h  (8192 w)
constexpr int EB1_OFF = EH_OFF + 128 * 64;     // 128 f32
constexpr int EB2_OFF = EB1_OFF + 128;         // 64 f32
constexpr int EDGE_SMEM = (EB2_OFF + 64) * 4;  // 197376 B

// ---- node smem layout (words) ---------------------------------------------
constexpr int NW1_OFF = 0;                     // [64 n][128 k]h
constexpr int NW2_OFF = NW1_OFF + 64 * 64;     // [64 n][64 k]h
constexpr int NX_OFF  = NW2_OFF + 64 * 32;     // [128 r][128 k]h
constexpr int NH_OFF  = NX_OFF + 128 * 64;     // [128 r][64 h]h
constexpr int NB1_OFF = NH_OFF + 128 * 32;     // 64 f32
constexpr int NB2_OFF = NB1_OFF + 64;          // 64 f32
constexpr int NODE_SMEM = (NB2_OFF + 64) * 4;  // 74240 B

__device__ __forceinline__ uint32_t p2h(float a, float b) {
    __half2 h = __floats2half2_rn(a, b);   // low = a
    return *(uint32_t*)&h;
}
__device__ __forceinline__ uint4 pack8(float4 a, float4 b) {
    uint4 r;
    r.x = p2h(a.x, a.y); r.y = p2h(a.z, a.w);
    r.z = p2h(b.x, b.y); r.w = p2h(b.z, b.w);
    return r;
}

__device__ __forceinline__ void mma16(float* c, uint32_t a0, uint32_t a1,
                                      uint32_t a2, uint32_t a3,
                                      uint32_t b0, uint32_t b1) {
    asm("mma.sync.aligned.m16n8k16.row.col.f32.f16.f16.f32 "
        "{%0,%1,%2,%3}, {%4,%5,%6,%7}, {%8,%9}, {%0,%1,%2,%3};"
        : "+f"(c[0]), "+f"(c[1]), "+f"(c[2]), "+f"(c[3])
        : "r"(a0), "r"(a1), "r"(a2), "r"(a3), "r"(b0), "r"(b1));
}

// XOR-swizzled 16B-chunk store: row stride in words, chunk = 16B unit index.
__device__ __forceinline__ void st_chunk(uint32_t* b, int row, int stride,
                                         int chunk, uint4 v) {
    const int c = (chunk & ~7) | ((chunk & 7) ^ (row & 7));
    *(uint4*)(b + row * stride + c * 4) = v;
}

// ---------------------------------------------------------------------------
// Edge MLP: x = [A[idxA[e]] | B[idxB[e]] | EF[e]] (192) -> relu(x@W1+b1) (128)
//           -> @W2+b2 (64) -> atomicAdd accum[idxOut[e]]
// Tile = 128 edges, 8 warps. GEMM1 warp: 32e x 64h. GEMM2 warp: 32e x 32o.
// X is double-buffered; next tile's gather is prefetched into registers
// right after barrier (1) and stored to the other buffer after GEMM2.
// ---------------------------------------------------------------------------
__global__ void __launch_bounds__(ETPB, 1) edge_mlp_tc(
    const float* __restrict__ A, const int* __restrict__ idxA,
    const float* __restrict__ B, const int* __restrict__ idxB,
    const float* __restrict__ EF, const int* __restrict__ idxOut,
    const float* __restrict__ W1, const float* __restrict__ b1,
    const float* __restrict__ W2, const float* __restrict__ b2,
    float* __restrict__ accum, float* __restrict__ deg, int E)
{
    extern __shared__ uint32_t smu[];
    uint32_t* W1s = smu + EW1_OFF;
    uint32_t* W2s = smu + EW2_OFF;
    uint32_t* Hs  = smu + EH_OFF;
    float* sB1 = (float*)(smu + EB1_OFF);
    float* sB2 = (float*)(smu + EB2_OFF);

    const int tid = threadIdx.x;
    const int warp = tid >> 5, lane = tid & 31;
    const int g = lane >> 2, t = lane & 3;

    // ---- one-time: weights -> [n][k] halves, swizzled ---------------------
    for (int i = tid; i < 96 * 128; i += ETPB) {
        const int kp = i >> 7, n = i & 127;
        const int ch = kp >> 2;
        const int cc = (ch & ~7) | ((ch & 7) ^ (n & 7));
        W1s[n * 96 + cc * 4 + (kp & 3)] =
            p2h(W1[(2 * kp) * 128 + n], W1[(2 * kp + 1) * 128 + n]);
    }
    for (int i = tid; i < 64 * 64; i += ETPB) {
        const int kp = i >> 6, n = i & 63;
        const int ch = kp >> 2;
        const int cc = (ch & ~7) | ((ch & 7) ^ (n & 7));
        W2s[n * 64 + cc * 4 + (kp & 3)] =
            p2h(W2[(2 * kp) * 64 + n], W2[(2 * kp + 1) * 64 + n]);
    }
    if (tid < 128) sB1[tid] = b1[tid];
    if (tid < 64)  sB2[tid] = b2[tid];

    int off3[8];
    #pragma unroll
    for (int c = 0; c < 8; c++) off3[c] = ((c ^ g) << 2) + t;

    const int m0 = (warp >> 1) * 32;
    const int n0 = (warp & 1) * 64;
    const int nb = (warp & 1) * 32;

    int arA[2][2], arH[2][2], brB[8], br2[4];
    #pragma unroll
    for (int mi = 0; mi < 2; mi++) {
        arA[mi][0] = (m0 + mi * 16 + g) * 96;
        arA[mi][1] = (m0 + mi * 16 + g + 8) * 96;
        arH[mi][0] = (m0 + mi * 16 + g) * 64;
        arH[mi][1] = (m0 + mi * 16 + g + 8) * 64;
    }
    #pragma unroll
    for (int ni = 0; ni < 8; ni++) brB[ni] = (n0 + ni * 8 + g) * 96;
    #pragma unroll
    for (int ni = 0; ni < 4; ni++) br2[ni] = (nb + ni * 8 + g) * 64;

    const int el = tid >> 1, half = tid & 1;
    const int cA = half * 8;            // A/B chunk base
    const int cE = 16 + half * 4;       // EF chunk base
    const int ntiles = (E + 127) >> 7;

    uint32_t* Xc = smu + EX0_OFF;
    uint32_t* Xn = smu + EX1_OFF;

    int tile = blockIdx.x;

    // ---- prologue: stage tile0 directly into Xc ----
    if (tile < ntiles) {
        const int ge = (tile << 7) + el;
        if (ge < E) {
            const float4* s1 = (half == 0)
                ? (const float4*)(A + (size_t)idxA[ge] * HD)
                : (const float4*)(B + (size_t)idxB[ge] * HD);
            const float4* ef = (const float4*)(EF + (size_t)ge * HD) + half * 8;
            #pragma unroll
            for (int j = 0; j < 8; j++)
                st_chunk(Xc, el, 96, cA + j, pack8(s1[2 * j], s1[2 * j + 1]));
            #pragma unroll
            for (int j = 0; j < 4; j++)
                st_chunk(Xc, el, 96, cE + j, pack8(ef[2 * j], ef[2 * j + 1]));
        }
    }

    for (; tile < ntiles; tile += gridDim.x) {
        const int base = tile << 7;
        const int ntile = tile + gridDim.x;
        __syncthreads();   // (1) Xc ready (also covers weight staging, 1st iter)

        // ---- prefetch next tile's gather into registers (latency hidden) --
        float4 pa[16], pe[8];
        const int nge = (ntile << 7) + el;
        const bool pval = (ntile < ntiles) && (nge < E);
        if (pval) {
            const float4* s1 = (half == 0)
                ? (const float4*)(A + (size_t)idxA[nge] * HD)
                : (const float4*)(B + (size_t)idxB[nge] * HD);
            #pragma unroll
            for (int j = 0; j < 16; j++) pa[j] = s1[j];
            const float4* ef = (const float4*)(EF + (size_t)nge * HD) + half * 8;
            #pragma unroll
            for (int j = 0; j < 8; j++) pe[j] = ef[j];
        }

        // ---- GEMM1: 32e x 64h, K=192 (12 k16 steps) ----
        float c1[2][8][4];
        #pragma unroll
        for (int mi = 0; mi < 2; mi++)
            #pragma unroll
            for (int ni = 0; ni < 8; ni++)
                #pragma unroll
                for (int p = 0; p < 4; p++) c1[mi][ni][p] = 0.0f;

        #pragma unroll
        for (int ks = 0; ks < 12; ks++) {
            const int C0 = 2 * ks, C1 = 2 * ks + 1;
            const int o0 = ((C0 & ~7) << 2) + off3[C0 & 7];
            const int o1 = ((C1 & ~7) << 2) + off3[C1 & 7];
            uint32_t a[2][4];
            #pragma unroll
            for (int mi = 0; mi < 2; mi++) {
                a[mi][0] = Xc[arA[mi][0] + o0];
                a[mi][1] = Xc[arA[mi][1] + o0];
                a[mi][2] = Xc[arA[mi][0] + o1];
                a[mi][3] = Xc[arA[mi][1] + o1];
            }
            uint32_t b[8][2];
            #pragma unroll
            for (int ni = 0; ni < 8; ni++) {
                b[ni][0] = W1s[brB[ni] + o0];
                b[ni][1] = W1s[brB[ni] + o1];
            }
            #pragma unroll
            for (int mi = 0; mi < 2; mi++)
                #pragma unroll
                for (int ni = 0; ni < 8; ni++)
                    mma16(c1[mi][ni], a[mi][0], a[mi][1], a[mi][2], a[mi][3],
                          b[ni][0], b[ni][1]);
        }

        // ---- epilogue 1: relu(c1 + b1) -> H (fp16, swizzled) ----
        #pragma unroll
        for (int mi = 0; mi < 2; mi++) {
            const int r0 = m0 + mi * 16 + g;
            #pragma unroll
            for (int ni = 0; ni < 8; ni++) {
                const int col = n0 + ni * 8 + 2 * t;
                const float2 bb = *(const float2*)(sB1 + col);
                const int ch = (n0 >> 3) + ni;
                const int cc = (ch & ~7) | ((ch & 7) ^ g);
                const int wo = cc * 4 + t;
                Hs[r0 * 64 + wo] =
                    p2h(fmaxf(c1[mi][ni][0] + bb.x, 0.0f),
                        fmaxf(c1[mi][ni][1] + bb.y, 0.0f));
                Hs[(r0 + 8) * 64 + wo] =
                    p2h(fmaxf(c1[mi][ni][2] + bb.x, 0.0f),
                        fmaxf(c1[mi][ni][3] + bb.y, 0.0f));
            }
        }
        if (deg != nullptr && tid < 128) {
            const int ge = base + tid;
            if (ge < E) atomicAdd(deg + idxA[ge], 1.0f);
        }
        __syncthreads();   // (2) H ready (Xc reads also all done)

        // ---- GEMM2: 32e x 32o, K=128 (8 k16 steps) ----
        float c2[2][4][4];
        #pragma unroll
        for (int mi = 0; mi < 2; mi++)
            #pragma unroll
            for (int ni = 0; ni < 4; ni++)
                #pragma unroll
                for (int p = 0; p < 4; p++) c2[mi][ni][p] = 0.0f;

        #pragma unroll
        for (int ks = 0; ks < 8; ks++) {
            const int C0 = 2 * ks, C1 = 2 * ks + 1;
            const int o0 = ((C0 & ~7) << 2) + off3[C0 & 7];
            const int o1 = ((C1 & ~7) << 2) + off3[C1 & 7];
            uint32_t a[2][4];
            #pragma unroll
            for (int mi = 0; mi < 2; mi++) {
                a[mi][0] = Hs[arH[mi][0] + o0];
                a[mi][1] = Hs[arH[mi][1] + o0];
                a[mi][2] = Hs[arH[mi][0] + o1];
                a[mi][3] = Hs[arH[mi][1] + o1];
            }
            uint32_t b[4][2];
            #pragma unroll
            for (int ni = 0; ni < 4; ni++) {
                b[ni][0] = W2s[br2[ni] + o0];
                b[ni][1] = W2s[br2[ni] + o1];
            }
            #pragma unroll
            for (int mi = 0; mi < 2; mi++)
                #pragma unroll
                for (int ni = 0; ni < 4; ni++)
                    mma16(c2[mi][ni], a[mi][0], a[mi][1], a[mi][2], a[mi][3],
                          b[ni][0], b[ni][1]);
        }

        // ---- store prefetched next tile into Xn (readers long done) ----
        if (pval) {
            #pragma unroll
            for (int j = 0; j < 8; j++)
                st_chunk(Xn, el, 96, cA + j, pack8(pa[2 * j], pa[2 * j + 1]));
            #pragma unroll
            for (int j = 0; j < 4; j++)
                st_chunk(Xn, el, 96, cE + j, pack8(pe[2 * j], pe[2 * j + 1]));
        }

        // ---- epilogue 2: + b2, atomic scatter ----
        #pragma unroll
        for (int mi = 0; mi < 2; mi++) {
            const int r0 = m0 + mi * 16 + g;
            const int ge0 = base + r0, ge1 = ge0 + 8;
            const int d0 = (ge0 < E) ? idxOut[ge0] : -1;
            const int d1 = (ge1 < E) ? idxOut[ge1] : -1;
            #pragma unroll
            for (int ni = 0; ni < 4; ni++) {
                const int col = nb + ni * 8 + 2 * t;
                const float2 bb = *(const float2*)(sB2 + col);
                if (d0 >= 0) {
                    float* p = accum + (size_t)d0 * HD + col;
                    atomicAdd(p,     c2[mi][ni][0] + bb.x);
                    atomicAdd(p + 1, c2[mi][ni][1] + bb.y);
                }
                if (d1 >= 0) {
                    float* p = accum + (size_t)d1 * HD + col;
                    atomicAdd(p,     c2[mi][ni][2] + bb.x);
                    atomicAdd(p + 1, c2[mi][ni][3] + bb.y);
                }
            }
        }

        // swap buffers; barrier (1) of next iteration orders Xn stores
        uint32_t* tmp = Xc; Xc = Xn; Xn = tmp;
    }
}

// ---------------------------------------------------------------------------
// Node MLP: x = [self[i] | msum[i]*scale] (128) -> relu(x@W1+b1) (64)
//           -> @W2+b2 (64) -> direct store. 2 CTAs/SM.
// ---------------------------------------------------------------------------
__global__ void __launch_bounds__(NTPB, 2) node_mlp_tc(
    const float* __restrict__ selfF, const float* __restrict__ msum,
    const float* __restrict__ deg, const int* __restrict__ Sp,
    const float* __restrict__ W1, const float* __restrict__ b1,
    const float* __restrict__ W2, const float* __restrict__ b2,
    float* __restrict__ out, int N)
{
    extern __shared__ uint32_t smu[];
    uint32_t* W1s = smu + NW1_OFF;
    uint32_t* W2s = smu + NW2_OFF;
    uint32_t* Xs  = smu + NX_OFF;
    uint32_t* Hs  = smu + NH_OFF;
    float* sB1 = (float*)(smu + NB1_OFF);
    float* sB2 = (float*)(smu + NB2_OFF);

    const int tid = threadIdx.x;
    const int warp = tid >> 5, lane = tid & 31;
    const int g = lane >> 2, t = lane & 3;

    for (int i = tid; i < 64 * 64; i += NTPB) {
        const int kp = i >> 6, n = i & 63;
        const int ch = kp >> 2;
        const int cc = (ch & ~7) | ((ch & 7) ^ (n & 7));
        W1s[n * 64 + cc * 4 + (kp & 3)] =
            p2h(W1[(2 * kp) * 64 + n], W1[(2 * kp + 1) * 64 + n]);
    }
    for (int i = tid; i < 32 * 64; i += NTPB) {
        const int kp = i >> 6, n = i & 63;
        const int ch = kp >> 2;
        const int cc = (ch & ~7) | ((ch & 7) ^ (n & 7));
        W2s[n * 32 + cc * 4 + (kp & 3)] =
            p2h(W2[(2 * kp) * 64 + n], W2[(2 * kp + 1) * 64 + n]);
    }
    if (tid < 64) { sB1[tid] = b1[tid]; sB2[tid] = b2[tid]; }
    __syncthreads();

    const float invS = (Sp != nullptr) ? (1.0f / (float)(*Sp)) : 0.0f;

    int off3[8];
    #pragma unroll
    for (int c = 0; c < 8; c++) off3[c] = ((c ^ g) << 2) + t;

    const int m0 = (warp >> 1) * 32;
    const int n0 = (warp & 1) * 32;

    int arX[2][2], arH[2][2], brB[4], br2[4];
    #pragma unroll
    for (int mi = 0; mi < 2; mi++) {
        arX[mi][0] = (m0 + mi * 16 + g) * 64;
        arX[mi][1] = (m0 + mi * 16 + g + 8) * 64;
        arH[mi][0] = (m0 + mi * 16 + g) * 32;
        arH[mi][1] = (m0 + mi * 16 + g + 8) * 32;
    }
    #pragma unroll
    for (int ni = 0; ni < 4; ni++) {
        brB[ni] = (n0 + ni * 8 + g) * 64;
        br2[ni] = (n0 + ni * 8 + g) * 32;
    }

    const int sr = tid >> 1, half = tid & 1;
    const int ntiles = (N + 127) >> 7;

    for (int tile = blockIdx.x; tile < ntiles; tile += gridDim.x) {
        const int base = tile << 7;

        // ---- stage X [128 rows][16 chunks] ----
        {
            const int i = base + sr;
            if (i < N) {
                if (half == 0) {
                    const float4* s = (const float4*)(selfF + (size_t)i * HD);
                    #pragma unroll
                    for (int j = 0; j < 8; j++)
                        st_chunk(Xs, sr, 64, j, pack8(s[2 * j], s[2 * j + 1]));
                } else {
                    const float sc = (Sp != nullptr) ? invS
                                                     : (1.0f / fmaxf(deg[i], 1.0f));
                    const float4* m = (const float4*)(msum + (size_t)i * HD);
                    #pragma unroll
                    for (int j = 0; j < 8; j++) {
                        float4 v0 = m[2 * j], v1 = m[2 * j + 1];
                        v0.x *= sc; v0.y *= sc; v0.z *= sc; v0.w *= sc;
                        v1.x *= sc; v1.y *= sc; v1.z *= sc; v1.w *= sc;
                        st_chunk(Xs, sr, 64, 8 + j, pack8(v0, v1));
                    }
                }
            }
        }
        __syncthreads();   // (1) X ready

        // ---- GEMM1: 32r x 32h, K=128 (8 steps) ----
        float c1[2][4][4];
        #pragma unroll
        for (int mi = 0; mi < 2; mi++)
            #pragma unroll
            for (int ni = 0; ni < 4; ni++)
                #pragma unroll
                for (int p = 0; p < 4; p++) c1[mi][ni][p] = 0.0f;

        #pragma unroll
        for (int ks = 0; ks < 8; ks++) {
            const int C0 = 2 * ks, C1 = 2 * ks + 1;
            const int o0 = ((C0 & ~7) << 2) + off3[C0 & 7];
            const int o1 = ((C1 & ~7) << 2) + off3[C1 & 7];
            uint32_t a[2][4];
            #pragma unroll
            for (int mi = 0; mi < 2; mi++) {
                a[mi][0] = Xs[arX[mi][0] + o0];
                a[mi][1] = Xs[arX[mi][1] + o0];
                a[mi][2] = Xs[arX[mi][0] + o1];
                a[mi][3] = Xs[arX[mi][1] + o1];
            }
            uint32_t b[4][2];
            #pragma unroll
            for (int ni = 0; ni < 4; ni++) {
                b[ni][0] = W1s[brB[ni] + o0];
                b[ni][1] = W1s[brB[ni] + o1];
            }
            #pragma unroll
            for (int mi = 0; mi < 2; mi++)
                #pragma unroll
                for (int ni = 0; ni < 4; ni++)
                    mma16(c1[mi][ni], a[mi][0], a[mi][1], a[mi][2], a[mi][3],
                          b[ni][0], b[ni][1]);
        }

        // ---- epilogue 1: relu -> H (fp16, stride 32 words) ----
        #pragma unroll
        for (int mi = 0; mi < 2; mi++) {
            const int r0 = m0 + mi * 16 + g;
            #pragma unroll
            for (int ni = 0; ni < 4; ni++) {
                const int col = n0 + ni * 8 + 2 * t;
                const float2 bb = *(const float2*)(sB1 + col);
                const int ch = (n0 >> 3) + ni;
                const int cc = (ch & ~7) | ((ch & 7) ^ g);
                const int wo = cc * 4 + t;
                Hs[r0 * 32 + wo] =
                    p2h(fmaxf(c1[mi][ni][0] + bb.x, 0.0f),
                        fmaxf(c1[mi][ni][1] + bb.y, 0.0f));
                Hs[(r0 + 8) * 32 + wo] =
                    p2h(fmaxf(c1[mi][ni][2] + bb.x, 0.0f),
                        fmaxf(c1[mi][ni][3] + bb.y, 0.0f));
            }
        }
        __syncthreads();   // (2) H ready

        // ---- GEMM2: 32r x 32o, K=64 (4 steps) ----
        float c2[2][4][4];
        #pragma unroll
        for (int mi = 0; mi < 2; mi++)
            #pragma unroll
            for (int ni = 0; ni < 4; ni++)
                #pragma unroll
                for (int p = 0; p < 4; p++) c2[mi][ni][p] = 0.0f;

        #pragma unroll
        for (int ks = 0; ks < 4; ks++) {
            const int C0 = 2 * ks, C1 = 2 * ks + 1;
            const int o0 = ((C0 & ~7) << 2) + off3[C0 & 7];
            const int o1 = ((C1 & ~7) << 2) + off3[C1 & 7];
            uint32_t a[2][4];
            #pragma unroll
            for (int mi = 0; mi < 2; mi++) {
                a[mi][0] = Hs[arH[mi][0] + o0];
                a[mi][1] = Hs[arH[mi][1] + o0];
                a[mi][2] = Hs[arH[mi][0] + o1];
                a[mi][3] = Hs[arH[mi][1] + o1];
            }
            uint32_t b[4][2];
            #pragma unroll
            for (int ni = 0; ni < 4; ni++) {
                b[ni][0] = W2s[br2[ni] + o0];
                b[ni][1] = W2s[br2[ni] + o1];
            }
            #pragma unroll
            for (int mi = 0; mi < 2; mi++)
                #pragma unroll
                for (int ni = 0; ni < 4; ni++)
                    mma16(c2[mi][ni], a[mi][0], a[mi][1], a[mi][2], a[mi][3],
                          b[ni][0], b[ni][1]);
        }

        // ---- epilogue 2: + b2, direct store ----
        #pragma unroll
        for (int mi = 0; mi < 2; mi++) {
            const int r0 = m0 + mi * 16 + g;
            const int gi0 = base + r0, gi1 = gi0 + 8;
            #pragma unroll
            for (int ni = 0; ni < 4; ni++) {
                const int col = n0 + ni * 8 + 2 * t;
                const float2 bb = *(const float2*)(sB2 + col);
                if (gi0 < N)
                    *(float2*)(out + (size_t)gi0 * HD + col) =
                        make_float2(c2[mi][ni][0] + bb.x, c2[mi][ni][1] + bb.y);
                if (gi1 < N)
                    *(float2*)(out + (size_t)gi1 * HD + col) =
                        make_float2(c2[mi][ni][2] + bb.x, c2[mi][ni][3] + bb.y);
            }
        }
        __syncthreads();   // H reads done before next tile staging
    }
}

// ---------------------------------------------------------------------------
extern "C" void kernel_launch(void* const* d_in, const int* in_sizes, int n_in,
                              void* d_out, int out_size)
{
    const float* h_v    = (const float*)d_in[0];
    const float* h_u    = (const float*)d_in[1];
    const float* e_feat = (const float*)d_in[2];
    const int*   ei     = (const int*)d_in[3];
    const int*   Sp     = (const int*)d_in[4];
    const float* a2u_w1 = (const float*)d_in[5];
    const float* a2u_b1 = (const float*)d_in[6];
    const float* a2u_w2 = (const float*)d_in[7];
    const float* a2u_b2 = (const float*)d_in[8];
    const float* u_w1   = (const float*)d_in[9];
    const float* u_b1   = (const float*)d_in[10];
    const float* u_w2   = (const float*)d_in[11];
    const float* u_b2   = (const float*)d_in[12];
    const float* u2a_w1 = (const float*)d_in[13];
    const float* u2a_b1 = (const float*)d_in[14];
    const float* u2a_w2 = (const float*)d_in[15];
    const float* u2a_b2 = (const float*)d_in[16];
    const float* a_w1   = (const float*)d_in[17];
    const float* a_b1   = (const float*)d_in[18];
    const float* a_w2   = (const float*)d_in[19];
    const float* a_b2   = (const float*)d_in[20];

    const int NVn = in_sizes[0] / HD;
    const int NUn = in_sizes[1] / HD;
    const int E   = in_sizes[3] / 2;
    const int* src = ei;
    const int* dst = ei + E;

    float *m_u = nullptr, *m_v = nullptr, *degp = nullptr;
    cudaGetSymbolAddress((void**)&m_u, g_m_u);
    cudaGetSymbolAddress((void**)&m_v, g_m_v);
    cudaGetSymbolAddress((void**)&degp, g_deg);

    int sms = 148;
    cudaDeviceGetAttribute(&sms, cudaDevAttrMultiProcessorCount, 0);

    cudaFuncSetAttribute(edge_mlp_tc,
                         cudaFuncAttributeMaxDynamicSharedMemorySize, EDGE_SMEM);
    cudaFuncSetAttribute(node_mlp_tc,
                         cudaFuncAttributeMaxDynamicSharedMemorySize, NODE_SMEM);

    cudaMemsetAsync(m_u,  0, (size_t)NUn * HD * sizeof(float));
    cudaMemsetAsync(m_v,  0, (size_t)NVn * HD * sizeof(float));
    cudaMemsetAsync(degp, 0, (size_t)NVn * sizeof(float));

    float* h_v_out = (float*)d_out;
    float* h_u_out = (float*)d_out + (size_t)NVn * HD;

    const int etiles = (E + 127) >> 7;
    const int egrid = etiles < sms ? etiles : sms;
    const int nutiles = (NUn + 127) >> 7;
    const int nvtiles = (NVn + 127) >> 7;
    const int ngrid_u = nutiles < 2 * sms ? nutiles : 2 * sms;
    const int ngrid_v = nvtiles < 2 * sms ? nvtiles : 2 * sms;

    // Pass 1: a -> u messages, scatter to m_u[dst]; count deg[src]
    edge_mlp_tc<<<egrid, ETPB, EDGE_SMEM>>>(
        h_v, src, h_u, dst, e_feat, dst,
        a2u_w1, a2u_b1, a2u_w2, a2u_b2, m_u, degp, E);

    // u node update
    node_mlp_tc<<<ngrid_u, NTPB, NODE_SMEM>>>(
        h_u, m_u, nullptr, Sp,
        u_w1, u_b1, u_w2, u_b2, h_u_out, NUn);

    // Pass 2: u -> a messages, scatter to m_v[src]
    edge_mlp_tc<<<egrid, ETPB, EDGE_SMEM>>>(
        h_u_out, dst, h_v, src, e_feat, src,
        u2a_w1, u2a_b1, u2a_w2, u2a_b2, m_v, nullptr, E);

    // v node update
    node_mlp_tc<<<ngrid_v, NTPB, NODE_SMEM>>>(
        h_v, m_v, degp, nullptr,
        a_w1, a_b1, a_w2, a_b2, h_v_out, NVn);
}